// round 1
// baseline (speedup 1.0000x reference)
#include <cuda_runtime.h>
#include <math.h>

// PatchRepulsionLoss: pcs [8192, 2048, 3] f32 -> scalar f32
// B=8192, P=32 patches, n=64 points/patch, N_SIGMA=1
// loss = sum_{b} sum_{i<=j} || relu(std_i+std_j - |mean_i-mean_j|) ||_2 / (528*B)

#define NPATCH 32
#define PTS_PER_PATCH 64
#define FLOATS_PER_BATCH (2048 * 3)   // 6144 floats = 24 KB
#define NTHREADS 256
#define NBATCH 8192

__global__ void prl_zero_kernel(float* out) {
    out[0] = 0.0f;
}

__global__ void __launch_bounds__(NTHREADS)
prl_main_kernel(const float* __restrict__ pcs, float* __restrict__ out) {
    __shared__ float4 sdata4[FLOATS_PER_BATCH / 4];   // 1536 float4 = 24 KB
    __shared__ float s_mean[NPATCH * 3];
    __shared__ float s_std[NPATCH * 3];
    __shared__ float s_part[8];

    const int tid = threadIdx.x;
    const int b = blockIdx.x;

    // --- Load batch slice to smem, fully coalesced float4 ---
    const float4* gin = reinterpret_cast<const float4*>(pcs) +
                        (size_t)b * (FLOATS_PER_BATCH / 4);
#pragma unroll
    for (int k = 0; k < FLOATS_PER_BATCH / 4 / NTHREADS; k++) {
        sdata4[tid + k * NTHREADS] = gin[tid + k * NTHREADS];
    }
    __syncthreads();
    const float* sdata = reinterpret_cast<const float*>(sdata4);

    const int warp = tid >> 5;
    const int lane = tid & 31;

    // --- Per-patch stats: warp w handles patches 4w .. 4w+3 ---
    // Each lane reads 2 points (6 floats) of the patch, warp-reduces sum & sumsq.
#pragma unroll
    for (int pi = 0; pi < 4; pi++) {
        const int p = warp * 4 + pi;
        const float* base = sdata + p * (PTS_PER_PATCH * 3) + lane * 6;
        float f0 = base[0], f1 = base[1], f2 = base[2];
        float f3 = base[3], f4 = base[4], f5 = base[5];
        float s0 = f0 + f3, s1 = f1 + f4, s2 = f2 + f5;
        float q0 = f0 * f0 + f3 * f3;
        float q1 = f1 * f1 + f4 * f4;
        float q2 = f2 * f2 + f5 * f5;
#pragma unroll
        for (int off = 16; off; off >>= 1) {
            s0 += __shfl_xor_sync(0xFFFFFFFFu, s0, off);
            s1 += __shfl_xor_sync(0xFFFFFFFFu, s1, off);
            s2 += __shfl_xor_sync(0xFFFFFFFFu, s2, off);
            q0 += __shfl_xor_sync(0xFFFFFFFFu, q0, off);
            q1 += __shfl_xor_sync(0xFFFFFFFFu, q1, off);
            q2 += __shfl_xor_sync(0xFFFFFFFFu, q2, off);
        }
        if (lane == 0) {
            const float inv_n = 1.0f / 64.0f;
            const float inv_nm1 = 1.0f / 63.0f;
            s_mean[p * 3 + 0] = s0 * inv_n;
            s_mean[p * 3 + 1] = s1 * inv_n;
            s_mean[p * 3 + 2] = s2 * inv_n;
            float v0 = (q0 - s0 * s0 * inv_n) * inv_nm1;
            float v1 = (q1 - s1 * s1 * inv_n) * inv_nm1;
            float v2 = (q2 - s2 * s2 * inv_n) * inv_nm1;
            s_std[p * 3 + 0] = sqrtf(fmaxf(v0, 0.0f));
            s_std[p * 3 + 1] = sqrtf(fmaxf(v1, 0.0f));
            s_std[p * 3 + 2] = sqrtf(fmaxf(v2, 0.0f));
        }
    }
    __syncthreads();

    // --- Pair phase: full symmetric 32x32 matrix.
    // sum over upper-tri incl diag = 0.5 * (full sum) + 0.5 * (diag sum)
    // => per-pair weight: 0.5, plus another 0.5 when i == j.
    float local = 0.0f;
#pragma unroll
    for (int k = 0; k < (NPATCH * NPATCH) / NTHREADS; k++) {
        const int id = tid + k * NTHREADS;
        const int i = id >> 5;   // constant within a warp (broadcast loads)
        const int j = id & 31;   // = lane, stride-3 smem access, conflict-free
        float acc = 0.0f;
#pragma unroll
        for (int d = 0; d < 3; d++) {
            float ssum = s_std[i * 3 + d] + s_std[j * 3 + d];
            float delta = fabsf(s_mean[i * 3 + d] - s_mean[j * 3 + d]);
            float rep = fmaxf(ssum - delta, 0.0f);
            acc = fmaf(rep, rep, acc);
        }
        float nrm = sqrtf(acc);
        local += (i == j) ? nrm : 0.5f * nrm;
    }

    // --- Block reduce ---
#pragma unroll
    for (int off = 16; off; off >>= 1)
        local += __shfl_xor_sync(0xFFFFFFFFu, local, off);
    if (lane == 0) s_part[warp] = local;
    __syncthreads();
    if (warp == 0) {
        float v = (lane < 8) ? s_part[lane] : 0.0f;
#pragma unroll
        for (int off = 4; off; off >>= 1)
            v += __shfl_xor_sync(0xFFFFFFFFu, v, off);
        if (lane == 0) {
            const float scale = 1.0f / (528.0f * (float)NBATCH);
            atomicAdd(out, v * scale);
        }
    }
}

extern "C" void kernel_launch(void* const* d_in, const int* in_sizes, int n_in,
                              void* d_out, int out_size) {
    const float* pcs = (const float*)d_in[0];
    float* out = (float*)d_out;
    prl_zero_kernel<<<1, 1>>>(out);
    prl_main_kernel<<<NBATCH, NTHREADS>>>(pcs, out);
}

// round 2
// speedup vs baseline: 1.6927x; 1.6927x over previous
#include <cuda_runtime.h>
#include <cstdint>
#include <math.h>

// PatchRepulsionLoss: pcs [8192, 2048, 3] f32 -> scalar f32
// B=8192, P=32 patches, n=64 points/patch, N_SIGMA=1
// loss = sum_b sum_{i<=j} || relu(std_i+std_j - |mean_i-mean_j|) ||_2 / (528*B)

#define NPATCH 32
#define FLOATS_PER_BATCH (2048 * 3)       // 6144 floats = 24 KB
#define BYTES_PER_BATCH  (FLOATS_PER_BATCH * 4)
#define NTHREADS 256
#define NBATCH 8192

__global__ void prl_zero_kernel(float* out) { out[0] = 0.0f; }

__device__ __forceinline__ uint32_t smem_u32(const void* p) {
    uint32_t a;
    asm("{ .reg .u64 t; cvta.to.shared.u64 t, %1; cvt.u32.u64 %0, t; }"
        : "=r"(a) : "l"(p));
    return a;
}

__global__ void __launch_bounds__(NTHREADS)
prl_main_kernel(const float* __restrict__ pcs, float* __restrict__ out) {
    __shared__ alignas(128) float4 sdata4[FLOATS_PER_BATCH / 4];  // 24 KB
    __shared__ alignas(8) uint64_t mbar;
    __shared__ float s_mean[NPATCH * 3];
    __shared__ float s_std[NPATCH * 3];
    __shared__ float s_part[8];

    const int tid = threadIdx.x;
    const int b = blockIdx.x;
    const uint32_t mbar_a = smem_u32(&mbar);
    const uint32_t dst_a = smem_u32(sdata4);

    if (tid == 0) {
        asm volatile("mbarrier.init.shared.b64 [%0], 1;" :: "r"(mbar_a) : "memory");
    }
    __syncthreads();

    if (tid == 0) {
        asm volatile("mbarrier.arrive.expect_tx.shared.b64 _, [%0], %1;"
                     :: "r"(mbar_a), "r"((uint32_t)BYTES_PER_BATCH) : "memory");
        const char* src = reinterpret_cast<const char*>(pcs) +
                          (size_t)b * BYTES_PER_BATCH;
        asm volatile(
            "cp.async.bulk.shared::cta.global.mbarrier::complete_tx::bytes "
            "[%0], [%1], %2, [%3];"
            :: "r"(dst_a), "l"(src), "r"((uint32_t)BYTES_PER_BATCH), "r"(mbar_a)
            : "memory");
    }

    // Wait for bulk copy (parity 0), acquire semantics
    {
        uint32_t done;
        asm volatile(
            "{\n\t.reg .pred p;\n\t"
            "mbarrier.try_wait.parity.acquire.cta.shared::cta.b64 p, [%1], 0;\n\t"
            "selp.b32 %0, 1, 0, p;\n\t}"
            : "=r"(done) : "r"(mbar_a) : "memory");
        if (!done) {
            asm volatile(
                "{\n\t.reg .pred P1;\n\t"
                "WL_%=:\n\t"
                "mbarrier.try_wait.parity.acquire.cta.shared::cta.b64 P1, [%0], 0, 0x989680;\n\t"
                "@P1 bra.uni WD_%=;\n\t"
                "bra.uni WL_%=;\n\t"
                "WD_%=:\n\t}"
                :: "r"(mbar_a) : "memory");
        }
    }

    // --- Stats: thread owns chunk c = tid -> floats [24c, 24c+24) = 8 whole
    // points, all inside patch p = c/8. Phase 0: float index % 3 gives dim.
    const int lane = tid & 31;
    const int warp = tid >> 5;

    float s0 = 0.f, s1 = 0.f, s2 = 0.f;   // per-dim sums
    float q0 = 0.f, q1 = 0.f, q2 = 0.f;   // per-dim sumsq
    const float4* chunk = sdata4 + tid * 6;
#pragma unroll
    for (int j = 0; j < 6; j++) {
        float4 v = chunk[j];
        // dims of (x,y,z,w) = (4j, 4j+1, 4j+2, 4j+3) mod 3 ; 4j mod 3 = j mod 3
        switch (j % 3) {
        case 0:
            s0 += v.x + v.w; s1 += v.y; s2 += v.z;
            q0 = fmaf(v.x, v.x, q0); q0 = fmaf(v.w, v.w, q0);
            q1 = fmaf(v.y, v.y, q1); q2 = fmaf(v.z, v.z, q2);
            break;
        case 1:
            s1 += v.x + v.w; s2 += v.y; s0 += v.z;
            q1 = fmaf(v.x, v.x, q1); q1 = fmaf(v.w, v.w, q1);
            q2 = fmaf(v.y, v.y, q2); q0 = fmaf(v.z, v.z, q0);
            break;
        default:
            s2 += v.x + v.w; s0 += v.y; s1 += v.z;
            q2 = fmaf(v.x, v.x, q2); q2 = fmaf(v.w, v.w, q2);
            q0 = fmaf(v.y, v.y, q0); q1 = fmaf(v.z, v.z, q1);
            break;
        }
    }

    // 8-lane group reduction (chunks 8p..8p+7 are one patch, lanes aligned)
#pragma unroll
    for (int off = 4; off; off >>= 1) {
        s0 += __shfl_xor_sync(0xFFFFFFFFu, s0, off);
        s1 += __shfl_xor_sync(0xFFFFFFFFu, s1, off);
        s2 += __shfl_xor_sync(0xFFFFFFFFu, s2, off);
        q0 += __shfl_xor_sync(0xFFFFFFFFu, q0, off);
        q1 += __shfl_xor_sync(0xFFFFFFFFu, q1, off);
        q2 += __shfl_xor_sync(0xFFFFFFFFu, q2, off);
    }
    if ((lane & 7) == 0) {
        const int p = tid >> 3;
        const float inv_n = 1.0f / 64.0f;
        const float inv_nm1 = 1.0f / 63.0f;
        s_mean[p * 3 + 0] = s0 * inv_n;
        s_mean[p * 3 + 1] = s1 * inv_n;
        s_mean[p * 3 + 2] = s2 * inv_n;
        float v0 = (q0 - s0 * s0 * inv_n) * inv_nm1;
        float v1 = (q1 - s1 * s1 * inv_n) * inv_nm1;
        float v2 = (q2 - s2 * s2 * inv_n) * inv_nm1;
        s_std[p * 3 + 0] = sqrtf(fmaxf(v0, 0.0f));
        s_std[p * 3 + 1] = sqrtf(fmaxf(v1, 0.0f));
        s_std[p * 3 + 2] = sqrtf(fmaxf(v2, 0.0f));
    }
    __syncthreads();

    // --- Pair phase: full 32x32 symmetric; upper-tri-incl-diag sum =
    // 0.5*full + 0.5*diag -> weight 0.5 off-diag, 1.0 on diag.
    float local = 0.0f;
#pragma unroll
    for (int k = 0; k < (NPATCH * NPATCH) / NTHREADS; k++) {
        const int id = tid + k * NTHREADS;
        const int i = id >> 5;   // uniform within warp (broadcast)
        const int j = id & 31;   // stride-3 words, conflict-free
        float acc = 0.0f;
#pragma unroll
        for (int d = 0; d < 3; d++) {
            float ssum = s_std[i * 3 + d] + s_std[j * 3 + d];
            float delta = fabsf(s_mean[i * 3 + d] - s_mean[j * 3 + d]);
            float rep = fmaxf(ssum - delta, 0.0f);
            acc = fmaf(rep, rep, acc);
        }
        float nrm = sqrtf(acc);
        local += (i == j) ? nrm : 0.5f * nrm;
    }

    // --- Block reduce ---
#pragma unroll
    for (int off = 16; off; off >>= 1)
        local += __shfl_xor_sync(0xFFFFFFFFu, local, off);
    if (lane == 0) s_part[warp] = local;
    __syncthreads();
    if (warp == 0) {
        float v = (lane < 8) ? s_part[lane] : 0.0f;
#pragma unroll
        for (int off = 4; off; off >>= 1)
            v += __shfl_xor_sync(0xFFFFFFFFu, v, off);
        if (lane == 0) {
            const float scale = 1.0f / (528.0f * (float)NBATCH);
            atomicAdd(out, v * scale);
        }
    }
}

extern "C" void kernel_launch(void* const* d_in, const int* in_sizes, int n_in,
                              void* d_out, int out_size) {
    const float* pcs = (const float*)d_in[0];
    float* out = (float*)d_out;
    prl_zero_kernel<<<1, 1>>>(out);
    prl_main_kernel<<<NBATCH, NTHREADS>>>(pcs, out);
}